// round 7
// baseline (speedup 1.0000x reference)
#include <cuda_runtime.h>
#include <cuda_bf16.h>
#include <math_constants.h>
#include <math.h>
#include <stdint.h>

#define Bc 16
#define Tc 1024
#define Sc 2048
#define Cc 256
#define Ec 256
#define NSEL 103     // ceil(2048/20)
#define MS 20
#define STRIDEc 20

// ---------------- scratch (device globals; no allocation allowed) ----------
__device__ float g_h[Bc*Tc*Ec];        // 16 MB; out1 (fp32)
__device__ __nv_bfloat16 g_hh[Bc*Tc*Ec], g_hl[Bc*Tc*Ec];          // h split
__device__ __nv_bfloat16 g_ekh[Bc*Ec*Sc], g_ekl[Bc*Ec*Sc];        // enc_keys split
__device__ __nv_bfloat16 g_evh[Bc*Sc*Ec], g_evl[Bc*Sc*Ec];        // enc_values split
__device__ __nv_bfloat16 g_ah[(size_t)Bc*Tc*Sc], g_al[(size_t)Bc*Tc*Sc]; // attn split
__device__ float g_xmean[Bc*Sc];
__device__ float g_invn[Bc*NSEL];
__device__ float g_aa[Bc*NSEL];
__device__ float g_L[Bc*NSEL*NSEL];
__device__ int   g_mu[Bc*MS];
__device__ float g_kl;

// ---------------- small init / final ---------------------------------------
__global__ void init_k() { g_kl = 0.0f; }
__global__ void final_k(float* klout) { klout[0] = -g_kl; }

// ---------------- tf32 split (bitmask) for the small weight GEMMs -----------
__device__ __forceinline__ void split_tf32(float x, uint32_t& hi, uint32_t& lo)
{
    uint32_t xb = __float_as_uint(x);
    uint32_t h  = xb & 0xFFFFE000u;
    hi = h;
    lo = __float_as_uint(x - __uint_as_float(h));
}

__device__ __forceinline__ void split_bf16(float x, __nv_bfloat16& h, __nv_bfloat16& l)
{
    h = __float2bfloat16(x);
    l = __float2bfloat16(x - __bfloat162float(h));
}

#define MMA_TF32(c, a, b) \
    asm volatile("mma.sync.aligned.m16n8k8.row.col.f32.tf32.tf32.f32 " \
        "{%0,%1,%2,%3}, {%4,%5,%6,%7}, {%8,%9}, {%0,%1,%2,%3};" \
        : "+f"((c)[0]), "+f"((c)[1]), "+f"((c)[2]), "+f"((c)[3]) \
        : "r"((a)[0]), "r"((a)[1]), "r"((a)[2]), "r"((a)[3]), \
          "r"((b)[0]), "r"((b)[1]))

#define MMA_BF16(c, a, b) \
    asm volatile("mma.sync.aligned.m16n8k16.row.col.f32.bf16.bf16.f32 " \
        "{%0,%1,%2,%3}, {%4,%5,%6,%7}, {%8,%9}, {%0,%1,%2,%3};" \
        : "+f"((c)[0]), "+f"((c)[1]), "+f"((c)[2]), "+f"((c)[3]) \
        : "r"((a)[0]), "r"((a)[1]), "r"((a)[2]), "r"((a)[3]), \
          "r"((b)[0]), "r"((b)[1]))

#define LDSM4(r, addr) \
    asm volatile("ldmatrix.sync.aligned.m8n8.x4.shared.b16 {%0,%1,%2,%3}, [%4];" \
        : "=r"((r)[0]), "=r"((r)[1]), "=r"((r)[2]), "=r"((r)[3]) : "r"(addr))

#define LDSM4T(r, addr) \
    asm volatile("ldmatrix.sync.aligned.m8n8.x4.trans.shared.b16 {%0,%1,%2,%3}, [%4];" \
        : "=r"((r)[0]), "=r"((r)[1]), "=r"((r)[2]), "=r"((r)[3]) : "r"(addr))

__device__ __forceinline__ void cpa16(void* smem_dst, const void* gsrc)
{
    uint32_t d = (uint32_t)__cvta_generic_to_shared(smem_dst);
    asm volatile("cp.async.cg.shared.global [%0], [%1], 16;" :: "r"(d), "l"(gsrc));
}
__device__ __forceinline__ void cpa16s(uint32_t d, const void* gsrc)
{
    asm volatile("cp.async.cg.shared.global [%0], [%1], 16;" :: "r"(d), "l"(gsrc));
}
__device__ __forceinline__ void cpa_commit() { asm volatile("cp.async.commit_group;"); }
__device__ __forceinline__ void cpa_wait0()  { asm volatile("cp.async.wait_group 0;"); }
__device__ __forceinline__ void cpa_wait1()  { asm volatile("cp.async.wait_group 1;"); }

// ============================================================================
// Batched NN GEMM, bf16 3-split, pre-split operands, 3-stage pipeline:
//   C = alpha * (Ah+Al)[M,K] @ (Bh+Bl)[K,N]   (lo*lo dropped)
// BM=128 BN=64 BK=32, 256 threads (8 warps: 4 in M x 2 in N), warp 32x32.
// One __syncthreads per k-iteration (safe with 3 smem stages).
// ============================================================================
#define NNB_AH 0
#define NNB_AL 10240
#define NNB_BH 20480
#define NNB_BL 25088
#define NNB_BUF 29696
#define NNB_STAGES 3
#define NNB_SMEM (NNB_STAGES*NNB_BUF)

__global__ __launch_bounds__(256, 2)
void gemm_nn_bf16(const __nv_bfloat16* __restrict__ Ah, const __nv_bfloat16* __restrict__ Al,
                  const __nv_bfloat16* __restrict__ Bh, const __nv_bfloat16* __restrict__ Bl,
                  float* __restrict__ C, int M, int N, int K,
                  long long sA, long long sB, long long sC, float alpha)
{
    extern __shared__ char smdyn[];
    const int bz = blockIdx.z;
    Ah += (size_t)bz * sA; Al += (size_t)bz * sA;
    Bh += (size_t)bz * sB; Bl += (size_t)bz * sB;
    C  += (size_t)bz * sC;
    const int m0 = blockIdx.y * 128, n0 = blockIdx.x * 64;
    const int tid = threadIdx.x, lane = tid & 31, wid = tid >> 5;
    const int wm = (wid & 3) * 32, wn = (wid >> 2) * 32;
    const int g = lane >> 2, t = lane & 3;
    const uint32_t sbase = (uint32_t)__cvta_generic_to_shared(smdyn);

    float c[2][4][4] = {};
    const int S = K / 32;

    auto issue = [&](int kt) {
        const uint32_t base = sbase + (kt % NNB_STAGES) * NNB_BUF;
        const int k0 = kt * 32;
        #pragma unroll
        for (int j = 0; j < 2; j++) {
            int ch = tid + j * 256, row = ch >> 2, cc = ch & 3;
            cpa16s(base + NNB_AH + row * 80 + cc * 16, Ah + (size_t)(m0 + row) * K + k0 + cc * 8);
            cpa16s(base + NNB_AL + row * 80 + cc * 16, Al + (size_t)(m0 + row) * K + k0 + cc * 8);
        }
        {
            int row = tid >> 3, cc = tid & 7;
            cpa16s(base + NNB_BH + row * 144 + cc * 16, Bh + (size_t)(k0 + row) * N + n0 + cc * 8);
            cpa16s(base + NNB_BL + row * 144 + cc * 16, Bl + (size_t)(k0 + row) * N + n0 + cc * 8);
        }
        cpa_commit();
    };

    issue(0);
    issue(1);
    for (int s = 0; s < S; s++) {
        if (s + 1 < S) cpa_wait1(); else cpa_wait0();
        __syncthreads();
        if (s + 2 < S) issue(s + 2);
        const uint32_t base = sbase + (s % NNB_STAGES) * NNB_BUF;
        #pragma unroll
        for (int ks = 0; ks < 2; ks++) {
            uint32_t aH[2][4], aL[2][4];
            #pragma unroll
            for (int mt = 0; mt < 2; mt++) {
                uint32_t addr = base + NNB_AH
                    + (uint32_t)(wm + mt * 16 + (lane & 15)) * 80
                    + (uint32_t)(ks * 32 + (lane >> 4) * 16);
                LDSM4(aH[mt], addr);
                LDSM4(aL[mt], addr + (NNB_AL - NNB_AH));
            }
            uint32_t bH[2][4], bL[2][4];
            #pragma unroll
            for (int bt = 0; bt < 2; bt++) {
                uint32_t addr = base + NNB_BH
                    + (uint32_t)(ks * 16 + (lane & 15)) * 144
                    + (uint32_t)((wn + bt * 16) * 2 + (lane >> 4) * 16);
                LDSM4T(bH[bt], addr);
                LDSM4T(bL[bt], addr + (NNB_BL - NNB_BH));
            }
            #pragma unroll
            for (int mt = 0; mt < 2; mt++)
                #pragma unroll
                for (int nt = 0; nt < 4; nt++) {
                    uint32_t* bh = &bH[nt >> 1][(nt & 1) * 2];
                    uint32_t* bl = &bL[nt >> 1][(nt & 1) * 2];
                    MMA_BF16(c[mt][nt], aH[mt], bh);
                    MMA_BF16(c[mt][nt], aH[mt], bl);
                    MMA_BF16(c[mt][nt], aL[mt], bh);
                }
        }
    }

    #pragma unroll
    for (int mt = 0; mt < 2; mt++)
        #pragma unroll
        for (int nt = 0; nt < 4; nt++) {
            int row = m0 + wm + mt * 16 + g;
            int col = n0 + wn + nt * 8 + 2 * t;
            float2 v0 = make_float2(alpha * c[mt][nt][0], alpha * c[mt][nt][1]);
            float2 v1 = make_float2(alpha * c[mt][nt][2], alpha * c[mt][nt][3]);
            *(float2*)&C[(size_t)row * N + col]       = v0;
            *(float2*)&C[(size_t)(row + 8) * N + col] = v1;
        }
}

// ============================================================================
// convert: fp32 -> bf16 hi/lo split arrays (vectorized)
// ============================================================================
__global__ void convert_split(const float4* __restrict__ src,
                              __nv_bfloat162* __restrict__ h2,
                              __nv_bfloat162* __restrict__ l2)
{
    const int i = blockIdx.x * 256 + threadIdx.x;
    float4 v = src[i];
    __nv_bfloat162 ha, hb, la, lb;
    split_bf16(v.x, ha.x, la.x); split_bf16(v.y, ha.y, la.y);
    split_bf16(v.z, hb.x, lb.x); split_bf16(v.w, hb.y, lb.y);
    h2[2*i] = ha; h2[2*i + 1] = hb;
    l2[2*i] = la; l2[2*i + 1] = lb;
}

// ============================================================================
// NT GEMM (tf32 split) producing split-bf16 h: h = (A @ W^T + bias + add)*scale
// ============================================================================
__global__ __launch_bounds__(256, 2)
void gemm_nt_h(const float* __restrict__ A, const float* __restrict__ W,
               const float* __restrict__ bias, const float* __restrict__ add,
               __nv_bfloat16* __restrict__ outh, __nv_bfloat16* __restrict__ outl,
               int M, int N, int K, float scale)
{
    const int m0 = blockIdx.y * 128, n0 = blockIdx.x * 64;
    const int tid = threadIdx.x, lane = tid & 31, wid = tid >> 5;
    const int wm = (wid & 3) * 32, wn = (wid >> 2) * 32;
    const int g = lane >> 2, t = lane & 3;

    __shared__ float As[2][128][20];
    __shared__ float Ws[2][64][20];

    float c[2][4][4] = {};
    const int S = K / 16;

    auto issue = [&](int s, int buf) {
        const int k0 = s * 16;
        #pragma unroll
        for (int j = 0; j < 2; j++) {
            int ch = tid + j * 256;
            int row = ch >> 2, kc = ch & 3;
            cpa16(&As[buf][row][kc * 4], A + (size_t)(m0 + row) * K + k0 + kc * 4);
        }
        int wrow = tid >> 2, wkc = tid & 3;
        cpa16(&Ws[buf][wrow][wkc * 4], W + (size_t)(n0 + wrow) * K + k0 + wkc * 4);
        cpa_commit();
    };

    issue(0, 0);
    for (int s = 0; s < S; s++) {
        if (s + 1 < S) { issue(s + 1, (s + 1) & 1); cpa_wait1(); }
        else cpa_wait0();
        __syncthreads();
        const int buf = s & 1;
        #pragma unroll
        for (int kf = 0; kf < 2; kf++) {
            uint32_t ah[2][4], al[2][4];
            #pragma unroll
            for (int mt = 0; mt < 2; mt++) {
                int mr = wm + mt * 16 + g;
                split_tf32(As[buf][mr    ][kf*8 + t],     ah[mt][0], al[mt][0]);
                split_tf32(As[buf][mr + 8][kf*8 + t],     ah[mt][1], al[mt][1]);
                split_tf32(As[buf][mr    ][kf*8 + t + 4], ah[mt][2], al[mt][2]);
                split_tf32(As[buf][mr + 8][kf*8 + t + 4], ah[mt][3], al[mt][3]);
            }
            uint32_t bh[4][2], bl[4][2];
            #pragma unroll
            for (int nt = 0; nt < 4; nt++) {
                int nr = wn + nt * 8 + g;
                split_tf32(Ws[buf][nr][kf*8 + t],     bh[nt][0], bl[nt][0]);
                split_tf32(Ws[buf][nr][kf*8 + t + 4], bh[nt][1], bl[nt][1]);
            }
            #pragma unroll
            for (int mt = 0; mt < 2; mt++)
                #pragma unroll
                for (int nt = 0; nt < 4; nt++) {
                    MMA_TF32(c[mt][nt], ah[mt], bh[nt]);
                    MMA_TF32(c[mt][nt], ah[mt], bl[nt]);
                    MMA_TF32(c[mt][nt], al[mt], bh[nt]);
                }
        }
        __syncthreads();
    }

    #pragma unroll
    for (int mt = 0; mt < 2; mt++)
        #pragma unroll
        for (int nt = 0; nt < 4; nt++) {
            int row = m0 + wm + mt * 16 + g;
            int col = n0 + wn + nt * 8 + 2 * t;
            float2 bv = *(const float2*)&bias[col];
            size_t i0 = (size_t)row * N + col;
            size_t i1 = (size_t)(row + 8) * N + col;
            float2 d0 = *(const float2*)&add[i0];
            float2 d1 = *(const float2*)&add[i1];
            float v00 = (c[mt][nt][0] + bv.x + d0.x) * scale;
            float v01 = (c[mt][nt][1] + bv.y + d0.y) * scale;
            float v10 = (c[mt][nt][2] + bv.x + d1.x) * scale;
            float v11 = (c[mt][nt][3] + bv.y + d1.y) * scale;
            __nv_bfloat162 h0, l0, h1, l1;
            split_bf16(v00, h0.x, l0.x); split_bf16(v01, h0.y, l0.y);
            split_bf16(v10, h1.x, l1.x); split_bf16(v11, h1.y, l1.y);
            *(__nv_bfloat162*)&outh[i0] = h0;
            *(__nv_bfloat162*)&outl[i0] = l0;
            *(__nv_bfloat162*)&outh[i1] = h1;
            *(__nv_bfloat162*)&outl[i1] = l1;
        }
}

// ============================================================================
// NT GEMM with fp32 epilogue (final output): out = (A @ W^T + bias + add)*scale
// ============================================================================
__global__ __launch_bounds__(256, 2)
void gemm_nt_tc(const float* __restrict__ A, const float* __restrict__ W,
                const float* __restrict__ bias, const float* __restrict__ add,
                float* __restrict__ out, int M, int N, int K, float scale)
{
    const int m0 = blockIdx.y * 128, n0 = blockIdx.x * 64;
    const int tid = threadIdx.x, lane = tid & 31, wid = tid >> 5;
    const int wm = (wid & 3) * 32, wn = (wid >> 2) * 32;
    const int g = lane >> 2, t = lane & 3;

    __shared__ float As[2][128][20];
    __shared__ float Ws[2][64][20];

    float c[2][4][4] = {};
    const int S = K / 16;

    auto issue = [&](int s, int buf) {
        const int k0 = s * 16;
        #pragma unroll
        for (int j = 0; j < 2; j++) {
            int ch = tid + j * 256;
            int row = ch >> 2, kc = ch & 3;
            cpa16(&As[buf][row][kc * 4], A + (size_t)(m0 + row) * K + k0 + kc * 4);
        }
        int wrow = tid >> 2, wkc = tid & 3;
        cpa16(&Ws[buf][wrow][wkc * 4], W + (size_t)(n0 + wrow) * K + k0 + wkc * 4);
        cpa_commit();
    };

    issue(0, 0);
    for (int s = 0; s < S; s++) {
        if (s + 1 < S) { issue(s + 1, (s + 1) & 1); cpa_wait1(); }
        else cpa_wait0();
        __syncthreads();
        const int buf = s & 1;
        #pragma unroll
        for (int kf = 0; kf < 2; kf++) {
            uint32_t ah[2][4], al[2][4];
            #pragma unroll
            for (int mt = 0; mt < 2; mt++) {
                int mr = wm + mt * 16 + g;
                split_tf32(As[buf][mr    ][kf*8 + t],     ah[mt][0], al[mt][0]);
                split_tf32(As[buf][mr + 8][kf*8 + t],     ah[mt][1], al[mt][1]);
                split_tf32(As[buf][mr    ][kf*8 + t + 4], ah[mt][2], al[mt][2]);
                split_tf32(As[buf][mr + 8][kf*8 + t + 4], ah[mt][3], al[mt][3]);
            }
            uint32_t bh[4][2], bl[4][2];
            #pragma unroll
            for (int nt = 0; nt < 4; nt++) {
                int nr = wn + nt * 8 + g;
                split_tf32(Ws[buf][nr][kf*8 + t],     bh[nt][0], bl[nt][0]);
                split_tf32(Ws[buf][nr][kf*8 + t + 4], bh[nt][1], bl[nt][1]);
            }
            #pragma unroll
            for (int mt = 0; mt < 2; mt++)
                #pragma unroll
                for (int nt = 0; nt < 4; nt++) {
                    MMA_TF32(c[mt][nt], ah[mt], bh[nt]);
                    MMA_TF32(c[mt][nt], ah[mt], bl[nt]);
                    MMA_TF32(c[mt][nt], al[mt], bh[nt]);
                }
        }
        __syncthreads();
    }

    #pragma unroll
    for (int mt = 0; mt < 2; mt++)
        #pragma unroll
        for (int nt = 0; nt < 4; nt++) {
            int row = m0 + wm + mt * 16 + g;
            int col = n0 + wn + nt * 8 + 2 * t;
            float2 bv = *(const float2*)&bias[col];
            size_t i0 = (size_t)row * N + col;
            size_t i1 = (size_t)(row + 8) * N + col;
            float2 d0 = *(const float2*)&add[i0];
            float2 d1 = *(const float2*)&add[i1];
            float2 v0 = make_float2((c[mt][nt][0] + bv.x + d0.x) * scale,
                                    (c[mt][nt][1] + bv.y + d0.y) * scale);
            float2 v1 = make_float2((c[mt][nt][2] + bv.x + d1.x) * scale,
                                    (c[mt][nt][3] + bv.y + d1.y) * scale);
            *(float2*)&out[i0] = v0;
            *(float2*)&out[i1] = v1;
        }
}

// ---------------- row softmax (in place) + bf16 hi/lo split output ----------
__global__ void softmax_split(float* __restrict__ attn,
                              __nv_bfloat16* __restrict__ ah,
                              __nv_bfloat16* __restrict__ al)
{
    const size_t row = blockIdx.x;
    float* p = attn + row * (size_t)Sc;
    __nv_bfloat16* ph = ah + row * (size_t)Sc;
    __nv_bfloat16* pl = al + row * (size_t)Sc;
    const int tid = threadIdx.x;   // 256 threads, 8 elems each
    __shared__ float red[256];
    float v[8];
    float mx = -CUDART_INF_F;
    #pragma unroll
    for (int i = 0; i < 8; i++) { v[i] = p[tid + i*256]; mx = fmaxf(mx, v[i]); }
    red[tid] = mx; __syncthreads();
    for (int s = 128; s > 0; s >>= 1) { if (tid < s) red[tid] = fmaxf(red[tid], red[tid+s]); __syncthreads(); }
    mx = red[0]; __syncthreads();
    float sum = 0.0f;
    #pragma unroll
    for (int i = 0; i < 8; i++) { v[i] = __expf(v[i] - mx); sum += v[i]; }
    red[tid] = sum; __syncthreads();
    for (int s = 128; s > 0; s >>= 1) { if (tid < s) red[tid] += red[tid+s]; __syncthreads(); }
    const float inv = 1.0f / red[0];
    #pragma unroll
    for (int i = 0; i < 8; i++) {
        float a = v[i] * inv;
        p[tid + i*256] = a;
        __nv_bfloat16 h, l;
        split_bf16(a, h, l);
        ph[tid + i*256] = h;
        pl[tid + i*256] = l;
    }
}

// ---------------- x_mean[b][s] = mean_t attn[b][t][s] -----------------------
__global__ void xmean_k(const float* __restrict__ attn)
{
    const int b = blockIdx.y;
    const int s = blockIdx.x * 256 + threadIdx.x;
    const float* p = attn + (size_t)b * Tc * Sc + s;
    float sum = 0.0f;
    for (int t = 0; t < Tc; t++) sum += p[(size_t)t * Sc];
    g_xmean[b * Sc + s] = sum * (1.0f / Tc);
}

// ---------------- row inv-norms of strided enc_values + aa -----------------
__global__ void norm_aa_k(const float* __restrict__ V)
{
    const int b = blockIdx.x;
    const int w = threadIdx.x >> 5, lane = threadIdx.x & 31;
    for (int n = w; n < NSEL; n += 8) {
        const float* row = V + ((size_t)b * Sc + (size_t)n * STRIDEc) * Ec;
        float s = 0.0f;
        for (int e = lane; e < Ec; e += 32) { float x = row[e]; s = fmaf(x, x, s); }
        #pragma unroll
        for (int o = 16; o; o >>= 1) s += __shfl_down_sync(0xffffffffu, s, o);
        if (lane == 0) {
            g_invn[b * NSEL + n] = rsqrtf(s);
            g_aa[b * NSEL + n]   = g_xmean[b * Sc + n * STRIDEc];
        }
    }
}

// ---------------- L[b][n][m] = aa_n aa_m * <v_n,v_m>/(|v_n||v_m|) ----------
__global__ void L_k(const float* __restrict__ V)
{
    const int b = blockIdx.x, n = blockIdx.y;
    __shared__ float vn[Ec];
    const float* rn = V + ((size_t)b * Sc + (size_t)n * STRIDEc) * Ec;
    for (int e = threadIdx.x; e < Ec; e += 128) vn[e] = rn[e];
    __syncthreads();
    const int m = threadIdx.x;
    if (m < NSEL) {
        const float* rm = V + ((size_t)b * Sc + (size_t)m * STRIDEc) * Ec;
        float d = 0.0f;
        for (int e = 0; e < Ec; e++) d = fmaf(vn[e], rm[e], d);
        float val = d * g_invn[b*NSEL + n] * g_invn[b*NSEL + m]
                      * g_aa[b*NSEL + n]   * g_aa[b*NSEL + m];
        g_L[((size_t)b * NSEL + n) * NSEL + m] = val;
    }
}

// numpy-style argmax of logf(D[n]*mask[n]): first NaN wins; strict > keeps first max
__device__ __forceinline__ int argmax_logDm(const float* D, const float* msk)
{
    int J = 0; float best = -CUDART_INF_F; bool done = false;
    for (int n = 0; n < NSEL && !done; n++) {
        float v = logf(D[n] * msk[n]);
        if (isnan(v)) { J = n; done = true; }
        else if (v > best) { best = v; J = n; }
    }
    return J;
}

// ---------------- greedy bfgm selection (sequential, tiny) -----------------
__global__ void bfgm_k()
{
    const int b = blockIdx.x, tid = threadIdx.x;  // 128 threads
    __shared__ float Cm[NSEL][MS];
    __shared__ float D[NSEL], msk[NSEL], cjs[MS];
    __shared__ float djs;
    __shared__ int Jsh, sel[MS];
    const float* L = g_L + (size_t)b * NSEL * NSEL;

    if (tid < NSEL) {
        D[tid] = L[(size_t)tid * NSEL + tid];
        msk[tid] = 1.0f;
        #pragma unroll
        for (int k = 0; k < MS; k++) Cm[tid][k] = 0.0f;
    }
    __syncthreads();
    if (tid == 0) {
        int J = argmax_logDm(D, msk);
        Jsh = J; msk[J] = 0.0f; sel[0] = J;
    }
    __syncthreads();

    for (int t = 1; t < MS; t++) {
        const int J = Jsh;
        if (tid < MS) cjs[tid] = Cm[J][tid];
        if (tid == 0) djs = D[J];
        __syncthreads();
        if (tid < NSEL) {
            float Lj = L[(size_t)J * NSEL + tid];
            float cd = 0.0f;
            #pragma unroll
            for (int k = 0; k < MS; k++) cd = fmaf(Cm[tid][k], cjs[k], cd);
            float e = (Lj - cd) / djs * msk[tid];
            Cm[tid][t] = e;
            D[tid] -= e * e;
        }
        __syncthreads();
        if (tid == 0) {
            int Jn = argmax_logDm(D, msk);
            Jsh = Jn; msk[Jn] = 0.0f; sel[t] = Jn;
        }
        __syncthreads();
    }
    if (tid == 0) {
        for (int i = 1; i < MS; i++) {          // insertion sort ascending
            int key = sel[i], j = i - 1;
            while (j >= 0 && sel[j] > key) { sel[j+1] = sel[j]; j--; }
            sel[j+1] = key;
        }
        for (int k = 0; k < MS; k++) g_mu[b*MS + k] = sel[k];
    }
}

// ---------------- gaussian mixture -> softmax(dist) -> KL partial ----------
__global__ void distkl_k()
{
    const int b = blockIdx.x, tid = threadIdx.x;   // 256 threads, 8 s-values each
    __shared__ float red[256];
    int mus[MS];
    #pragma unroll
    for (int k = 0; k < MS; k++) mus[k] = g_mu[b*MS + k];

    float g[8];
    float mx = -CUDART_INF_F;
    #pragma unroll
    for (int i = 0; i < 8; i++) {
        const int s = tid + i*256;
        float acc = 0.0f;
        #pragma unroll
        for (int k = 0; k < MS; k++) {
            float z = (float)s - (float)mus[k];
            acc += expf(-z*z * (1.0f/18.0f));        // 2*sigma^2 = 18
        }
        acc *= 0.13298076013381091f;                 // 1/(sqrt(2pi)*3)
        g[i] = acc; mx = fmaxf(mx, acc);
    }
    red[tid] = mx; __syncthreads();
    for (int s = 128; s > 0; s >>= 1) { if (tid < s) red[tid] = fmaxf(red[tid], red[tid+s]); __syncthreads(); }
    mx = red[0]; __syncthreads();
    float sum = 0.0f;
    #pragma unroll
    for (int i = 0; i < 8; i++) { g[i] = expf(g[i] - mx); sum += g[i]; }
    red[tid] = sum; __syncthreads();
    for (int s = 128; s > 0; s >>= 1) { if (tid < s) red[tid] += red[tid+s]; __syncthreads(); }
    const float inv = 1.0f / red[0];
    __syncthreads();

    float kl = 0.0f;
    #pragma unroll
    for (int i = 0; i < 8; i++) {
        const int s = tid + i*256;
        float xm = g_xmean[b*Sc + s];
        kl += xm * (logf(xm) - g[i] * inv);
    }
    red[tid] = kl; __syncthreads();
    for (int s = 128; s > 0; s >>= 1) { if (tid < s) red[tid] += red[tid+s]; __syncthreads(); }
    if (tid == 0) atomicAdd(&g_kl, red[0]);
}

// ---------------- launch ----------------------------------------------------
extern "C" void kernel_launch(void* const* d_in, const int* in_sizes, int n_in,
                              void* d_out, int out_size)
{
    const float* x  = (const float*)d_in[0];
    const float* te = (const float*)d_in[1];
    const float* ek = (const float*)d_in[2];   // [B,E,S]
    const float* ev = (const float*)d_in[3];   // [B,S,E]
    const float* Wi = (const float*)d_in[4];   // [E,C]
    const float* bi = (const float*)d_in[5];
    const float* Wo = (const float*)d_in[6];   // [C,E]
    const float* bo = (const float*)d_in[7];

    float* out  = (float*)d_out;                              // [B,T,C]
    float* attn = out + (size_t)Bc * Tc * Cc;                 // [B,T,S]
    float* klp  = attn + (size_t)Bc * Tc * Sc;                // scalar

    float* hbuf = nullptr;
    cudaGetSymbolAddress((void**)&hbuf, g_h);
    __nv_bfloat16 *hh, *hl, *ekh, *ekl, *evh, *evl, *ah, *al;
    cudaGetSymbolAddress((void**)&hh,  g_hh);
    cudaGetSymbolAddress((void**)&hl,  g_hl);
    cudaGetSymbolAddress((void**)&ekh, g_ekh);
    cudaGetSymbolAddress((void**)&ekl, g_ekl);
    cudaGetSymbolAddress((void**)&evh, g_evh);
    cudaGetSymbolAddress((void**)&evl, g_evl);
    cudaGetSymbolAddress((void**)&ah,  g_ah);
    cudaGetSymbolAddress((void**)&al,  g_al);

    cudaFuncSetAttribute(gemm_nn_bf16, cudaFuncAttributeMaxDynamicSharedMemorySize, NNB_SMEM);

    const float SQ05 = 0.70710678118654752f;
    const float SQS  = 45.25483399593904f;    // s*sqrt(1/s), s=2048

    init_k<<<1, 1>>>();

    // split ek, ev into bf16 hi/lo
    const int nEK4 = Bc * Ec * Sc / 4;  // per float4
    convert_split<<<nEK4 / 256, 256>>>((const float4*)ek, (__nv_bfloat162*)ekh, (__nv_bfloat162*)ekl);
    convert_split<<<nEK4 / 256, 256>>>((const float4*)ev, (__nv_bfloat162*)evh, (__nv_bfloat162*)evl);

    // h = (x @ W_in^T + b_in + te) * sqrt(0.5)  -> bf16 hi/lo
    gemm_nt_h<<<dim3(Ec/64, (Bc*Tc)/128), 256>>>(x, Wi, bi, te, hh, hl, Bc*Tc, Ec, Cc, SQ05);

    // scores = h @ enc_keys (bf16 3-split), write into attn region
    gemm_nn_bf16<<<dim3(Sc/64, Tc/128, Bc), 256, NNB_SMEM>>>(
        hh, hl, ekh, ekl, attn, Tc, Sc, Ec,
        (long long)Tc*Ec, (long long)Ec*Sc, (long long)Tc*Sc, 1.0f);

    // attn = softmax(scores) in place + bf16 hi/lo
    softmax_split<<<Bc*Tc, 256>>>(attn, ah, al);

    // x_mean
    xmean_k<<<dim3(Sc/256, Bc), 256>>>(attn);

    // out1 = attn @ enc_values * sqrt(S)  (bf16 3-split, fp32 out into g_h)
    gemm_nn_bf16<<<dim3(Ec/64, Tc/128, Bc), 256, NNB_SMEM>>>(
        ah, al, evh, evl, hbuf, Tc, Ec, Sc,
        (long long)Tc*Sc, (long long)Sc*Ec, (long long)Tc*Ec, SQS);

    // out = (out1 @ W_out^T + b_out + x) * sqrt(0.5)
    gemm_nt_tc<<<dim3(Cc/64, (Bc*Tc)/128), 256>>>(hbuf, Wo, bo, x, out, Bc*Tc, Cc, Ec, SQ05);

    // DPP side path
    norm_aa_k<<<Bc, 256>>>(ev);
    L_k<<<dim3(Bc, NSEL), 128>>>(ev);
    bfgm_k<<<Bc, 128>>>();
    distkl_k<<<Bc, 256>>>();
    final_k<<<1, 1>>>(klp);
}

// round 8
// speedup vs baseline: 1.0012x; 1.0012x over previous
#include <cuda_runtime.h>
#include <cuda_bf16.h>
#include <math_constants.h>
#include <math.h>
#include <stdint.h>

#define Bc 16
#define Tc 1024
#define Sc 2048
#define Cc 256
#define Ec 256
#define NSEL 103     // ceil(2048/20)
#define MS 20
#define STRIDEc 20

// ---------------- scratch (device globals; no allocation allowed) ----------
__device__ float g_h[Bc*Tc*Ec];        // 16 MB; out1 (fp32)
__device__ __nv_bfloat16 g_hh[Bc*Tc*Ec], g_hl[Bc*Tc*Ec];          // h split
__device__ __nv_bfloat16 g_ekh[Bc*Ec*Sc], g_ekl[Bc*Ec*Sc];        // enc_keys split
__device__ __nv_bfloat16 g_evh[Bc*Sc*Ec], g_evl[Bc*Sc*Ec];        // enc_values split
__device__ __nv_bfloat16 g_ah[(size_t)Bc*Tc*Sc], g_al[(size_t)Bc*Tc*Sc]; // attn split
__device__ float g_xmean[Bc*Sc];
__device__ float g_invn[Bc*NSEL];
__device__ float g_aa[Bc*NSEL];
__device__ float g_L[Bc*NSEL*NSEL];
__device__ int   g_mu[Bc*MS];
__device__ float g_kl;

// ---------------- small init / final ---------------------------------------
__global__ void init_k() { g_kl = 0.0f; }
__global__ void final_k(float* klout) { klout[0] = -g_kl; }

// ---------------- tf32 split (bitmask) for the small weight GEMMs -----------
__device__ __forceinline__ void split_tf32(float x, uint32_t& hi, uint32_t& lo)
{
    uint32_t xb = __float_as_uint(x);
    uint32_t h  = xb & 0xFFFFE000u;
    hi = h;
    lo = __float_as_uint(x - __uint_as_float(h));
}

__device__ __forceinline__ void split_bf16(float x, __nv_bfloat16& h, __nv_bfloat16& l)
{
    h = __float2bfloat16(x);
    l = __float2bfloat16(x - __bfloat162float(h));
}

#define MMA_TF32(c, a, b) \
    asm volatile("mma.sync.aligned.m16n8k8.row.col.f32.tf32.tf32.f32 " \
        "{%0,%1,%2,%3}, {%4,%5,%6,%7}, {%8,%9}, {%0,%1,%2,%3};" \
        : "+f"((c)[0]), "+f"((c)[1]), "+f"((c)[2]), "+f"((c)[3]) \
        : "r"((a)[0]), "r"((a)[1]), "r"((a)[2]), "r"((a)[3]), \
          "r"((b)[0]), "r"((b)[1]))

#define MMA_BF16(c, a, b) \
    asm volatile("mma.sync.aligned.m16n8k16.row.col.f32.bf16.bf16.f32 " \
        "{%0,%1,%2,%3}, {%4,%5,%6,%7}, {%8,%9}, {%0,%1,%2,%3};" \
        : "+f"((c)[0]), "+f"((c)[1]), "+f"((c)[2]), "+f"((c)[3]) \
        : "r"((a)[0]), "r"((a)[1]), "r"((a)[2]), "r"((a)[3]), \
          "r"((b)[0]), "r"((b)[1]))

#define LDSM4(r, addr) \
    asm volatile("ldmatrix.sync.aligned.m8n8.x4.shared.b16 {%0,%1,%2,%3}, [%4];" \
        : "=r"((r)[0]), "=r"((r)[1]), "=r"((r)[2]), "=r"((r)[3]) : "r"(addr))

#define LDSM4T(r, addr) \
    asm volatile("ldmatrix.sync.aligned.m8n8.x4.trans.shared.b16 {%0,%1,%2,%3}, [%4];" \
        : "=r"((r)[0]), "=r"((r)[1]), "=r"((r)[2]), "=r"((r)[3]) : "r"(addr))

__device__ __forceinline__ void cpa16(void* smem_dst, const void* gsrc)
{
    uint32_t d = (uint32_t)__cvta_generic_to_shared(smem_dst);
    asm volatile("cp.async.cg.shared.global [%0], [%1], 16;" :: "r"(d), "l"(gsrc));
}
__device__ __forceinline__ void cpa16s(uint32_t d, const void* gsrc)
{
    asm volatile("cp.async.cg.shared.global [%0], [%1], 16;" :: "r"(d), "l"(gsrc));
}
__device__ __forceinline__ void cpa_commit() { asm volatile("cp.async.commit_group;"); }
__device__ __forceinline__ void cpa_wait0()  { asm volatile("cp.async.wait_group 0;"); }
__device__ __forceinline__ void cpa_wait1()  { asm volatile("cp.async.wait_group 1;"); }

// ============================================================================
// Batched NN GEMM, bf16 3-split, pre-split operands, 3-stage pipeline:
//   C = alpha * (Ah+Al)[M,K] @ (Bh+Bl)[K,N]   (lo*lo dropped)
// BM=128 BN=64 BK=32, 256 threads (8 warps: 4 in M x 2 in N), warp 32x32.
// MMAs issued TERM-MAJOR: all independent accumulators back-to-back, so no
// same-accumulator RAW chains in the issue stream.
// ============================================================================
#define NNB_AH 0
#define NNB_AL 10240
#define NNB_BH 20480
#define NNB_BL 25088
#define NNB_BUF 29696
#define NNB_STAGES 3
#define NNB_SMEM (NNB_STAGES*NNB_BUF)

__global__ __launch_bounds__(256, 2)
void gemm_nn_bf16(const __nv_bfloat16* __restrict__ Ah, const __nv_bfloat16* __restrict__ Al,
                  const __nv_bfloat16* __restrict__ Bh, const __nv_bfloat16* __restrict__ Bl,
                  float* __restrict__ C, int M, int N, int K,
                  long long sA, long long sB, long long sC, float alpha)
{
    extern __shared__ char smdyn[];
    const int bz = blockIdx.z;
    Ah += (size_t)bz * sA; Al += (size_t)bz * sA;
    Bh += (size_t)bz * sB; Bl += (size_t)bz * sB;
    C  += (size_t)bz * sC;
    const int m0 = blockIdx.y * 128, n0 = blockIdx.x * 64;
    const int tid = threadIdx.x, lane = tid & 31, wid = tid >> 5;
    const int wm = (wid & 3) * 32, wn = (wid >> 2) * 32;
    const int g = lane >> 2, t = lane & 3;
    const uint32_t sbase = (uint32_t)__cvta_generic_to_shared(smdyn);

    float c[2][4][4] = {};
    const int S = K / 32;

    auto issue = [&](int kt) {
        const uint32_t base = sbase + (kt % NNB_STAGES) * NNB_BUF;
        const int k0 = kt * 32;
        #pragma unroll
        for (int j = 0; j < 2; j++) {
            int ch = tid + j * 256, row = ch >> 2, cc = ch & 3;
            cpa16s(base + NNB_AH + row * 80 + cc * 16, Ah + (size_t)(m0 + row) * K + k0 + cc * 8);
            cpa16s(base + NNB_AL + row * 80 + cc * 16, Al + (size_t)(m0 + row) * K + k0 + cc * 8);
        }
        {
            int row = tid >> 3, cc = tid & 7;
            cpa16s(base + NNB_BH + row * 144 + cc * 16, Bh + (size_t)(k0 + row) * N + n0 + cc * 8);
            cpa16s(base + NNB_BL + row * 144 + cc * 16, Bl + (size_t)(k0 + row) * N + n0 + cc * 8);
        }
        cpa_commit();
    };

    issue(0);
    issue(1);
    for (int s = 0; s < S; s++) {
        if (s + 1 < S) cpa_wait1(); else cpa_wait0();
        __syncthreads();
        if (s + 2 < S) issue(s + 2);
        const uint32_t base = sbase + (s % NNB_STAGES) * NNB_BUF;
        #pragma unroll
        for (int ks = 0; ks < 2; ks++) {
            uint32_t aH[2][4], aL[2][4];
            #pragma unroll
            for (int mt = 0; mt < 2; mt++) {
                uint32_t addr = base + NNB_AH
                    + (uint32_t)(wm + mt * 16 + (lane & 15)) * 80
                    + (uint32_t)(ks * 32 + (lane >> 4) * 16);
                LDSM4(aH[mt], addr);
                LDSM4(aL[mt], addr + (NNB_AL - NNB_AH));
            }
            uint32_t bH[2][4], bL[2][4];
            #pragma unroll
            for (int bt = 0; bt < 2; bt++) {
                uint32_t addr = base + NNB_BH
                    + (uint32_t)(ks * 16 + (lane & 15)) * 144
                    + (uint32_t)((wn + bt * 16) * 2 + (lane >> 4) * 16);
                LDSM4T(bH[bt], addr);
                LDSM4T(bL[bt], addr + (NNB_BL - NNB_BH));
            }
            // term-major: 8 independent accumulators per term, no RAW chains
            #pragma unroll
            for (int mt = 0; mt < 2; mt++)
                #pragma unroll
                for (int nt = 0; nt < 4; nt++)
                    MMA_BF16(c[mt][nt], aH[mt], (&bH[nt >> 1][(nt & 1) * 2]));
            #pragma unroll
            for (int mt = 0; mt < 2; mt++)
                #pragma unroll
                for (int nt = 0; nt < 4; nt++)
                    MMA_BF16(c[mt][nt], aH[mt], (&bL[nt >> 1][(nt & 1) * 2]));
            #pragma unroll
            for (int mt = 0; mt < 2; mt++)
                #pragma unroll
                for (int nt = 0; nt < 4; nt++)
                    MMA_BF16(c[mt][nt], aL[mt], (&bH[nt >> 1][(nt & 1) * 2]));
        }
    }

    #pragma unroll
    for (int mt = 0; mt < 2; mt++)
        #pragma unroll
        for (int nt = 0; nt < 4; nt++) {
            int row = m0 + wm + mt * 16 + g;
            int col = n0 + wn + nt * 8 + 2 * t;
            float2 v0 = make_float2(alpha * c[mt][nt][0], alpha * c[mt][nt][1]);
            float2 v1 = make_float2(alpha * c[mt][nt][2], alpha * c[mt][nt][3]);
            *(float2*)&C[(size_t)row * N + col]       = v0;
            *(float2*)&C[(size_t)(row + 8) * N + col] = v1;
        }
}

// ============================================================================
// convert: fp32 -> bf16 hi/lo split arrays (vectorized)
// ============================================================================
__global__ void convert_split(const float4* __restrict__ src,
                              __nv_bfloat162* __restrict__ h2,
                              __nv_bfloat162* __restrict__ l2)
{
    const int i = blockIdx.x * 256 + threadIdx.x;
    float4 v = src[i];
    __nv_bfloat162 ha, hb, la, lb;
    split_bf16(v.x, ha.x, la.x); split_bf16(v.y, ha.y, la.y);
    split_bf16(v.z, hb.x, lb.x); split_bf16(v.w, hb.y, lb.y);
    h2[2*i] = ha; h2[2*i + 1] = hb;
    l2[2*i] = la; l2[2*i + 1] = lb;
}

// ============================================================================
// NT GEMM (tf32 split) producing split-bf16 h: h = (A @ W^T + bias + add)*scale
// ============================================================================
__global__ __launch_bounds__(256, 2)
void gemm_nt_h(const float* __restrict__ A, const float* __restrict__ W,
               const float* __restrict__ bias, const float* __restrict__ add,
               __nv_bfloat16* __restrict__ outh, __nv_bfloat16* __restrict__ outl,
               int M, int N, int K, float scale)
{
    const int m0 = blockIdx.y * 128, n0 = blockIdx.x * 64;
    const int tid = threadIdx.x, lane = tid & 31, wid = tid >> 5;
    const int wm = (wid & 3) * 32, wn = (wid >> 2) * 32;
    const int g = lane >> 2, t = lane & 3;

    __shared__ float As[2][128][20];
    __shared__ float Ws[2][64][20];

    float c[2][4][4] = {};
    const int S = K / 16;

    auto issue = [&](int s, int buf) {
        const int k0 = s * 16;
        #pragma unroll
        for (int j = 0; j < 2; j++) {
            int ch = tid + j * 256;
            int row = ch >> 2, kc = ch & 3;
            cpa16(&As[buf][row][kc * 4], A + (size_t)(m0 + row) * K + k0 + kc * 4);
        }
        int wrow = tid >> 2, wkc = tid & 3;
        cpa16(&Ws[buf][wrow][wkc * 4], W + (size_t)(n0 + wrow) * K + k0 + wkc * 4);
        cpa_commit();
    };

    issue(0, 0);
    for (int s = 0; s < S; s++) {
        if (s + 1 < S) { issue(s + 1, (s + 1) & 1); cpa_wait1(); }
        else cpa_wait0();
        __syncthreads();
        const int buf = s & 1;
        #pragma unroll
        for (int kf = 0; kf < 2; kf++) {
            uint32_t ah[2][4], al[2][4];
            #pragma unroll
            for (int mt = 0; mt < 2; mt++) {
                int mr = wm + mt * 16 + g;
                split_tf32(As[buf][mr    ][kf*8 + t],     ah[mt][0], al[mt][0]);
                split_tf32(As[buf][mr + 8][kf*8 + t],     ah[mt][1], al[mt][1]);
                split_tf32(As[buf][mr    ][kf*8 + t + 4], ah[mt][2], al[mt][2]);
                split_tf32(As[buf][mr + 8][kf*8 + t + 4], ah[mt][3], al[mt][3]);
            }
            uint32_t bh[4][2], bl[4][2];
            #pragma unroll
            for (int nt = 0; nt < 4; nt++) {
                int nr = wn + nt * 8 + g;
                split_tf32(Ws[buf][nr][kf*8 + t],     bh[nt][0], bl[nt][0]);
                split_tf32(Ws[buf][nr][kf*8 + t + 4], bh[nt][1], bl[nt][1]);
            }
            // term-major ordering
            #pragma unroll
            for (int mt = 0; mt < 2; mt++)
                #pragma unroll
                for (int nt = 0; nt < 4; nt++)
                    MMA_TF32(c[mt][nt], ah[mt], bh[nt]);
            #pragma unroll
            for (int mt = 0; mt < 2; mt++)
                #pragma unroll
                for (int nt = 0; nt < 4; nt++)
                    MMA_TF32(c[mt][nt], ah[mt], bl[nt]);
            #pragma unroll
            for (int mt = 0; mt < 2; mt++)
                #pragma unroll
                for (int nt = 0; nt < 4; nt++)
                    MMA_TF32(c[mt][nt], al[mt], bh[nt]);
        }
        __syncthreads();
    }

    #pragma unroll
    for (int mt = 0; mt < 2; mt++)
        #pragma unroll
        for (int nt = 0; nt < 4; nt++) {
            int row = m0 + wm + mt * 16 + g;
            int col = n0 + wn + nt * 8 + 2 * t;
            float2 bv = *(const float2*)&bias[col];
            size_t i0 = (size_t)row * N + col;
            size_t i1 = (size_t)(row + 8) * N + col;
            float2 d0 = *(const float2*)&add[i0];
            float2 d1 = *(const float2*)&add[i1];
            float v00 = (c[mt][nt][0] + bv.x + d0.x) * scale;
            float v01 = (c[mt][nt][1] + bv.y + d0.y) * scale;
            float v10 = (c[mt][nt][2] + bv.x + d1.x) * scale;
            float v11 = (c[mt][nt][3] + bv.y + d1.y) * scale;
            __nv_bfloat162 h0, l0, h1, l1;
            split_bf16(v00, h0.x, l0.x); split_bf16(v01, h0.y, l0.y);
            split_bf16(v10, h1.x, l1.x); split_bf16(v11, h1.y, l1.y);
            *(__nv_bfloat162*)&outh[i0] = h0;
            *(__nv_bfloat162*)&outl[i0] = l0;
            *(__nv_bfloat162*)&outh[i1] = h1;
            *(__nv_bfloat162*)&outl[i1] = l1;
        }
}

// ============================================================================
// NT GEMM with fp32 epilogue (final output): out = (A @ W^T + bias + add)*scale
// ============================================================================
__global__ __launch_bounds__(256, 2)
void gemm_nt_tc(const float* __restrict__ A, const float* __restrict__ W,
                const float* __restrict__ bias, const float* __restrict__ add,
                float* __restrict__ out, int M, int N, int K, float scale)
{
    const int m0 = blockIdx.y * 128, n0 = blockIdx.x * 64;
    const int tid = threadIdx.x, lane = tid & 31, wid = tid >> 5;
    const int wm = (wid & 3) * 32, wn = (wid >> 2) * 32;
    const int g = lane >> 2, t = lane & 3;

    __shared__ float As[2][128][20];
    __shared__ float Ws[2][64][20];

    float c[2][4][4] = {};
    const int S = K / 16;

    auto issue = [&](int s, int buf) {
        const int k0 = s * 16;
        #pragma unroll
        for (int j = 0; j < 2; j++) {
            int ch = tid + j * 256;
            int row = ch >> 2, kc = ch & 3;
            cpa16(&As[buf][row][kc * 4], A + (size_t)(m0 + row) * K + k0 + kc * 4);
        }
        int wrow = tid >> 2, wkc = tid & 3;
        cpa16(&Ws[buf][wrow][wkc * 4], W + (size_t)(n0 + wrow) * K + k0 + wkc * 4);
        cpa_commit();
    };

    issue(0, 0);
    for (int s = 0; s < S; s++) {
        if (s + 1 < S) { issue(s + 1, (s + 1) & 1); cpa_wait1(); }
        else cpa_wait0();
        __syncthreads();
        const int buf = s & 1;
        #pragma unroll
        for (int kf = 0; kf < 2; kf++) {
            uint32_t ah[2][4], al[2][4];
            #pragma unroll
            for (int mt = 0; mt < 2; mt++) {
                int mr = wm + mt * 16 + g;
                split_tf32(As[buf][mr    ][kf*8 + t],     ah[mt][0], al[mt][0]);
                split_tf32(As[buf][mr + 8][kf*8 + t],     ah[mt][1], al[mt][1]);
                split_tf32(As[buf][mr    ][kf*8 + t + 4], ah[mt][2], al[mt][2]);
                split_tf32(As[buf][mr + 8][kf*8 + t + 4], ah[mt][3], al[mt][3]);
            }
            uint32_t bh[4][2], bl[4][2];
            #pragma unroll
            for (int nt = 0; nt < 4; nt++) {
                int nr = wn + nt * 8 + g;
                split_tf32(Ws[buf][nr][kf*8 + t],     bh[nt][0], bl[nt][0]);
                split_tf32(Ws[buf][nr][kf*8 + t + 4], bh[nt][1], bl[nt][1]);
            }
            // term-major ordering
            #pragma unroll
            for (int mt = 0; mt < 2; mt++)
                #pragma unroll
                for (int nt = 0; nt < 4; nt++)
                    MMA_TF32(c[mt][nt], ah[mt], bh[nt]);
            #pragma unroll
            for (int mt = 0; mt < 2; mt++)
                #pragma unroll
                for (int nt = 0; nt < 4; nt++)
                    MMA_TF32(c[mt][nt], ah[mt], bl[nt]);
            #pragma unroll
            for (int mt = 0; mt < 2; mt++)
                #pragma unroll
                for (int nt = 0; nt < 4; nt++)
                    MMA_TF32(c[mt][nt], al[mt], bh[nt]);
        }
        __syncthreads();
    }

    #pragma unroll
    for (int mt = 0; mt < 2; mt++)
        #pragma unroll
        for (int nt = 0; nt < 4; nt++) {
            int row = m0 + wm + mt * 16 + g;
            int col = n0 + wn + nt * 8 + 2 * t;
            float2 bv = *(const float2*)&bias[col];
            size_t i0 = (size_t)row * N + col;
            size_t i1 = (size_t)(row + 8) * N + col;
            float2 d0 = *(const float2*)&add[i0];
            float2 d1 = *(const float2*)&add[i1];
            float2 v0 = make_float2((c[mt][nt][0] + bv.x + d0.x) * scale,
                                    (c[mt][nt][1] + bv.y + d0.y) * scale);
            float2 v1 = make_float2((c[mt][nt][2] + bv.x + d1.x) * scale,
                                    (c[mt][nt][3] + bv.y + d1.y) * scale);
            *(float2*)&out[i0] = v0;
            *(float2*)&out[i1] = v1;
        }
}

// ---------------- row softmax (in place) + bf16 hi/lo split output ----------
__global__ void softmax_split(float* __restrict__ attn,
                              __nv_bfloat16* __restrict__ ah,
                              __nv_bfloat16* __restrict__ al)
{
    const size_t row = blockIdx.x;
    float* p = attn + row * (size_t)Sc;
    __nv_bfloat16* ph = ah + row * (size_t)Sc;
    __nv_bfloat16* pl = al + row * (size_t)Sc;
    const int tid = threadIdx.x;   // 256 threads, 8 elems each
    __shared__ float red[256];
    float v[8];
    float mx = -CUDART_INF_F;
    #pragma unroll
    for (int i = 0; i < 8; i++) { v[i] = p[tid + i*256]; mx = fmaxf(mx, v[i]); }
    red[tid] = mx; __syncthreads();
    for (int s = 128; s > 0; s >>= 1) { if (tid < s) red[tid] = fmaxf(red[tid], red[tid+s]); __syncthreads(); }
    mx = red[0]; __syncthreads();
    float sum = 0.0f;
    #pragma unroll
    for (int i = 0; i < 8; i++) { v[i] = __expf(v[i] - mx); sum += v[i]; }
    red[tid] = sum; __syncthreads();
    for (int s = 128; s > 0; s >>= 1) { if (tid < s) red[tid] += red[tid+s]; __syncthreads(); }
    const float inv = 1.0f / red[0];
    #pragma unroll
    for (int i = 0; i < 8; i++) {
        float a = v[i] * inv;
        p[tid + i*256] = a;
        __nv_bfloat16 h, l;
        split_bf16(a, h, l);
        ph[tid + i*256] = h;
        pl[tid + i*256] = l;
    }
}

// ---------------- x_mean[b][s] = mean_t attn[b][t][s] -----------------------
__global__ void xmean_k(const float* __restrict__ attn)
{
    const int b = blockIdx.y;
    const int s = blockIdx.x * 256 + threadIdx.x;
    const float* p = attn + (size_t)b * Tc * Sc + s;
    float sum = 0.0f;
    for (int t = 0; t < Tc; t++) sum += p[(size_t)t * Sc];
    g_xmean[b * Sc + s] = sum * (1.0f / Tc);
}

// ---------------- row inv-norms of strided enc_values + aa -----------------
__global__ void norm_aa_k(const float* __restrict__ V)
{
    const int b = blockIdx.x;
    const int w = threadIdx.x >> 5, lane = threadIdx.x & 31;
    for (int n = w; n < NSEL; n += 8) {
        const float* row = V + ((size_t)b * Sc + (size_t)n * STRIDEc) * Ec;
        float s = 0.0f;
        for (int e = lane; e < Ec; e += 32) { float x = row[e]; s = fmaf(x, x, s); }
        #pragma unroll
        for (int o = 16; o; o >>= 1) s += __shfl_down_sync(0xffffffffu, s, o);
        if (lane == 0) {
            g_invn[b * NSEL + n] = rsqrtf(s);
            g_aa[b * NSEL + n]   = g_xmean[b * Sc + n * STRIDEc];
        }
    }
}

// ---------------- L[b][n][m] = aa_n aa_m * <v_n,v_m>/(|v_n||v_m|) ----------
__global__ void L_k(const float* __restrict__ V)
{
    const int b = blockIdx.x, n = blockIdx.y;
    __shared__ float vn[Ec];
    const float* rn = V + ((size_t)b * Sc + (size_t)n * STRIDEc) * Ec;
    for (int e = threadIdx.x; e < Ec; e += 128) vn[e] = rn[e];
    __syncthreads();
    const int m = threadIdx.x;
    if (m < NSEL) {
        const float* rm = V + ((size_t)b * Sc + (size_t)m * STRIDEc) * Ec;
        float d = 0.0f;
        for (int e = 0; e < Ec; e++) d = fmaf(vn[e], rm[e], d);
        float val = d * g_invn[b*NSEL + n] * g_invn[b*NSEL + m]
                      * g_aa[b*NSEL + n]   * g_aa[b*NSEL + m];
        g_L[((size_t)b * NSEL + n) * NSEL + m] = val;
    }
}

// numpy-style argmax of logf(D[n]*mask[n]): first NaN wins; strict > keeps first max
__device__ __forceinline__ int argmax_logDm(const float* D, const float* msk)
{
    int J = 0; float best = -CUDART_INF_F; bool done = false;
    for (int n = 0; n < NSEL && !done; n++) {
        float v = logf(D[n] * msk[n]);
        if (isnan(v)) { J = n; done = true; }
        else if (v > best) { best = v; J = n; }
    }
    return J;
}

// ---------------- greedy bfgm selection (sequential, tiny) -----------------
__global__ void bfgm_k()
{
    const int b = blockIdx.x, tid = threadIdx.x;  // 128 threads
    __shared__ float Cm[NSEL][MS];
    __shared__ float D[NSEL], msk[NSEL], cjs[MS];
    __shared__ float djs;
    __shared__ int Jsh, sel[MS];
    const float* L = g_L + (size_t)b * NSEL * NSEL;

    if (tid < NSEL) {
        D[tid] = L[(size_t)tid * NSEL + tid];
        msk[tid] = 1.0f;
        #pragma unroll
        for (int k = 0; k < MS; k++) Cm[tid][k] = 0.0f;
    }
    __syncthreads();
    if (tid == 0) {
        int J = argmax_logDm(D, msk);
        Jsh = J; msk[J] = 0.0f; sel[0] = J;
    }
    __syncthreads();

    for (int t = 1; t < MS; t++) {
        const int J = Jsh;
        if (tid < MS) cjs[tid] = Cm[J][tid];
        if (tid == 0) djs = D[J];
        __syncthreads();
        if (tid < NSEL) {
            float Lj = L[(size_t)J * NSEL + tid];
            float cd = 0.0f;
            #pragma unroll
            for (int k = 0; k < MS; k++) cd = fmaf(Cm[tid][k], cjs[k], cd);
            float e = (Lj - cd) / djs * msk[tid];
            Cm[tid][t] = e;
            D[tid] -= e * e;
        }
        __syncthreads();
        if (tid == 0) {
            int Jn = argmax_logDm(D, msk);
            Jsh = Jn; msk[Jn] = 0.0f; sel[t] = Jn;
        }
        __syncthreads();
    }
    if (tid == 0) {
        for (int i = 1; i < MS; i++) {          // insertion sort ascending
            int key = sel[i], j = i - 1;
            while (j >= 0 && sel[j] > key) { sel[j+1] = sel[j]; j--; }
            sel[j+1] = key;
        }
        for (int k = 0; k < MS; k++) g_mu[b*MS + k] = sel[k];
    }
}

// ---------------- gaussian mixture -> softmax(dist) -> KL partial ----------
__global__ void distkl_k()
{
    const int b = blockIdx.x, tid = threadIdx.x;   // 256 threads, 8 s-values each
    __shared__ float red[256];
    int mus[MS];
    #pragma unroll
    for (int k = 0; k < MS; k++) mus[k] = g_mu[b*MS + k];

    float g[8];
    float mx = -CUDART_INF_F;
    #pragma unroll
    for (int i = 0; i < 8; i++) {
        const int s = tid + i*256;
        float acc = 0.0f;
        #pragma unroll
        for (int k = 0; k < MS; k++) {
            float z = (float)s - (float)mus[k];
            acc += expf(-z*z * (1.0f/18.0f));        // 2*sigma^2 = 18
        }
        acc *= 0.13298076013381091f;                 // 1/(sqrt(2pi)*3)
        g[i] = acc; mx = fmaxf(mx, acc);
    }
    red[tid] = mx; __syncthreads();
    for (int s = 128; s > 0; s >>= 1) { if (tid < s) red[tid] = fmaxf(red[tid], red[tid+s]); __syncthreads(); }
    mx = red[0]; __syncthreads();
    float sum = 0.0f;
    #pragma unroll
    for (int i = 0; i < 8; i++) { g[i] = expf(g[i] - mx); sum += g[i]; }
    red[tid] = sum; __syncthreads();
    for (int s = 128; s > 0; s >>= 1) { if (tid < s) red[tid] += red[tid+s]; __syncthreads(); }
    const float inv = 1.0f / red[0];
    __syncthreads();

    float kl = 0.0f;
    #pragma unroll
    for (int i = 0; i < 8; i++) {
        const int s = tid + i*256;
        float xm = g_xmean[b*Sc + s];
        kl += xm * (logf(xm) - g[i] * inv);
    }
    red[tid] = kl; __syncthreads();
    for (int s = 128; s > 0; s >>= 1) { if (tid < s) red[tid] += red[tid+s]; __syncthreads(); }
    if (tid == 0) atomicAdd(&g_kl, red[0]);
}

// ---------------- launch ----------------------------------------------------
extern "C" void kernel_launch(void* const* d_in, const int* in_sizes, int n_in,
                              void* d_out, int out_size)
{
    const float* x  = (const float*)d_in[0];
    const float* te = (const float*)d_in[1];
    const float* ek = (const float*)d_in[2];   // [B,E,S]
    const float* ev = (const float*)d_in[3];   // [B,S,E]
    const float* Wi = (const float*)d_in[4];   // [E,C]
    const float* bi = (const float*)d_in[5];
    const float* Wo = (const float*)d_in[6];   // [C,E]
    const float* bo = (const float*)d_in[7];

    float* out  = (float*)d_out;                              // [B,T,C]
    float* attn = out + (size_t)Bc * Tc * Cc;                 // [B,T,S]
    float* klp  = attn + (size_t)Bc * Tc * Sc;                // scalar

    float* hbuf = nullptr;
    cudaGetSymbolAddress((void**)&hbuf, g_h);
    __nv_bfloat16 *hh, *hl, *ekh, *ekl, *evh, *evl, *ah, *al;
    cudaGetSymbolAddress((void**)&hh,  g_hh);
    cudaGetSymbolAddress((void**)&hl,  g_hl);
    cudaGetSymbolAddress((void**)&ekh, g_ekh);
    cudaGetSymbolAddress((void**)&ekl, g_ekl);
    cudaGetSymbolAddress((void**)&evh, g_evh);
    cudaGetSymbolAddress((void**)&evl, g_evl);
    cudaGetSymbolAddress((void**)&ah,  g_ah);
    cudaGetSymbolAddress((void**)&al,  g_al);

    cudaFuncSetAttribute(gemm_nn_bf16, cudaFuncAttributeMaxDynamicSharedMemorySize, NNB_SMEM);

    const float SQ05 = 0.70710678118654752f;
    const float SQS  = 45.25483399593904f;    // s*sqrt(1/s), s=2048

    init_k<<<1, 1>>>();

    // split ek, ev into bf16 hi/lo
    const int nEK4 = Bc * Ec * Sc / 4;  // per float4
    convert_split<<<nEK4 / 256, 256>>>((const float4*)ek, (__nv_bfloat162*)ekh, (__nv_bfloat162*)ekl);
    convert_split<<<nEK4 / 256, 256>>>((const float4*)ev, (__nv_bfloat162*)evh, (__nv_bfloat162*)evl);

    // h = (x @ W_in^T + b_in + te) * sqrt(0.5)  -> bf16 hi/lo
    gemm_nt_h<<<dim3(Ec/64, (Bc*Tc)/128), 256>>>(x, Wi, bi, te, hh, hl, Bc*Tc, Ec, Cc, SQ05);

    // scores = h @ enc_keys (bf16 3-split), write into attn region
    gemm_nn_bf16<<<dim3(Sc/64, Tc/128, Bc), 256, NNB_SMEM>>>(
        hh, hl, ekh, ekl, attn, Tc, Sc, Ec,
        (long long)Tc*Ec, (long long)Ec*Sc, (long long)Tc*Sc, 1.0f);

    // attn = softmax(scores) in place + bf16 hi/lo
    softmax_split<<<Bc*Tc, 256>>>(attn, ah, al);

    // x_mean
    xmean_k<<<dim3(Sc/256, Bc), 256>>>(attn);

    // out1 = attn @ enc_values * sqrt(S)  (bf16 3-split, fp32 out into g_h)
    gemm_nn_bf16<<<dim3(Ec/64, Tc/128, Bc), 256, NNB_SMEM>>>(
        ah, al, evh, evl, hbuf, Tc, Ec, Sc,
        (long long)Tc*Sc, (long long)Sc*Ec, (long long)Tc*Ec, SQS);

    // out = (out1 @ W_out^T + b_out + x) * sqrt(0.5)
    gemm_nt_tc<<<dim3(Cc/64, (Bc*Tc)/128), 256>>>(hbuf, Wo, bo, x, out, Bc*Tc, Cc, Ec, SQ05);

    // DPP side path
    norm_aa_k<<<Bc, 256>>>(ev);
    L_k<<<dim3(Bc, NSEL), 128>>>(ev);
    bfgm_k<<<Bc, 128>>>();
    distkl_k<<<Bc, 256>>>();
    final_k<<<1, 1>>>(klp);
}

// round 9
// speedup vs baseline: 1.3208x; 1.3191x over previous
#include <cuda_runtime.h>
#include <cuda_fp16.h>
#include <math_constants.h>
#include <math.h>
#include <stdint.h>

#define Bc 16
#define Tc 1024
#define Sc 2048
#define Cc 256
#define Ec 256
#define NSEL 103     // ceil(2048/20)
#define MS 20
#define STRIDEc 20

// ---------------- scratch (device globals; no allocation allowed) ----------
__device__ float g_h[Bc*Tc*Ec];                 // out1 (fp32)
__device__ __half g_hf[Bc*Tc*Ec];               // h (fp16)
__device__ __half g_ekf[Bc*Ec*Sc];              // enc_keys fp16
__device__ __half g_evf[Bc*Sc*Ec];              // enc_values fp16
__device__ __half g_af[(size_t)Bc*Tc*Sc];       // attn fp16
__device__ float g_xmean[Bc*Sc];
__device__ float g_invn[Bc*NSEL];
__device__ float g_aa[Bc*NSEL];
__device__ float g_L[Bc*NSEL*NSEL];
__device__ int   g_mu[Bc*MS];
__device__ float g_kl;

// ---------------- small init / final ---------------------------------------
__global__ void init_k() { g_kl = 0.0f; }
__global__ void final_k(float* klout) { klout[0] = -g_kl; }

// ---------------- tf32 split (bitmask) for the weight GEMMs -----------------
__device__ __forceinline__ void split_tf32(float x, uint32_t& hi, uint32_t& lo)
{
    uint32_t xb = __float_as_uint(x);
    uint32_t h  = xb & 0xFFFFE000u;
    hi = h;
    lo = __float_as_uint(x - __uint_as_float(h));
}

#define MMA_TF32(c, a, b) \
    asm volatile("mma.sync.aligned.m16n8k8.row.col.f32.tf32.tf32.f32 " \
        "{%0,%1,%2,%3}, {%4,%5,%6,%7}, {%8,%9}, {%0,%1,%2,%3};" \
        : "+f"((c)[0]), "+f"((c)[1]), "+f"((c)[2]), "+f"((c)[3]) \
        : "r"((a)[0]), "r"((a)[1]), "r"((a)[2]), "r"((a)[3]), \
          "r"((b)[0]), "r"((b)[1]))

#define MMA_FP16(c, a, b) \
    asm volatile("mma.sync.aligned.m16n8k16.row.col.f32.f16.f16.f32 " \
        "{%0,%1,%2,%3}, {%4,%5,%6,%7}, {%8,%9}, {%0,%1,%2,%3};" \
        : "+f"((c)[0]), "+f"((c)[1]), "+f"((c)[2]), "+f"((c)[3]) \
        : "r"((a)[0]), "r"((a)[1]), "r"((a)[2]), "r"((a)[3]), \
          "r"((b)[0]), "r"((b)[1]))

#define LDSM4(r, addr) \
    asm volatile("ldmatrix.sync.aligned.m8n8.x4.shared.b16 {%0,%1,%2,%3}, [%4];" \
        : "=r"((r)[0]), "=r"((r)[1]), "=r"((r)[2]), "=r"((r)[3]) : "r"(addr))

#define LDSM4T(r, addr) \
    asm volatile("ldmatrix.sync.aligned.m8n8.x4.trans.shared.b16 {%0,%1,%2,%3}, [%4];" \
        : "=r"((r)[0]), "=r"((r)[1]), "=r"((r)[2]), "=r"((r)[3]) : "r"(addr))

__device__ __forceinline__ void cpa16(void* smem_dst, const void* gsrc)
{
    uint32_t d = (uint32_t)__cvta_generic_to_shared(smem_dst);
    asm volatile("cp.async.cg.shared.global [%0], [%1], 16;" :: "r"(d), "l"(gsrc));
}
__device__ __forceinline__ void cpa16s(uint32_t d, const void* gsrc)
{
    asm volatile("cp.async.cg.shared.global [%0], [%1], 16;" :: "r"(d), "l"(gsrc));
}
__device__ __forceinline__ void cpa_commit() { asm volatile("cp.async.commit_group;"); }
__device__ __forceinline__ void cpa_wait0()  { asm volatile("cp.async.wait_group 0;"); }
__device__ __forceinline__ void cpa_wait1()  { asm volatile("cp.async.wait_group 1;"); }

// ============================================================================
// Batched NN GEMM, single fp16, fp32 accumulate:  C = alpha * A[M,K] @ B[K,N]
// BM=128 BN=64 BK=32, 256 threads (8 warps: 4 in M x 2 in N), warp 32x32.
// 3-stage cp.async pipeline, one __syncthreads per k-iter.
// ============================================================================
#define NNF_A 0
#define NNF_B 10240
#define NNF_BUF 14848
#define NNF_STAGES 3
#define NNF_SMEM (NNF_STAGES*NNF_BUF)

__global__ __launch_bounds__(256, 2)
void gemm_nn_fp16(const __half* __restrict__ A, const __half* __restrict__ B,
                  float* __restrict__ C, int M, int N, int K,
                  long long sA, long long sB, long long sC, float alpha)
{
    extern __shared__ char smdyn[];
    const int bz = blockIdx.z;
    A += (size_t)bz * sA; B += (size_t)bz * sB; C += (size_t)bz * sC;
    const int m0 = blockIdx.y * 128, n0 = blockIdx.x * 64;
    const int tid = threadIdx.x, lane = tid & 31, wid = tid >> 5;
    const int wm = (wid & 3) * 32, wn = (wid >> 2) * 32;
    const int g = lane >> 2, t = lane & 3;
    const uint32_t sbase = (uint32_t)__cvta_generic_to_shared(smdyn);

    float c[2][4][4] = {};
    const int S = K / 32;

    auto issue = [&](int kt) {
        const uint32_t base = sbase + (kt % NNF_STAGES) * NNF_BUF;
        const int k0 = kt * 32;
        #pragma unroll
        for (int j = 0; j < 2; j++) {
            int ch = tid + j * 256, row = ch >> 2, cc = ch & 3;
            cpa16s(base + NNF_A + row * 80 + cc * 16, A + (size_t)(m0 + row) * K + k0 + cc * 8);
        }
        {
            int row = tid >> 3, cc = tid & 7;
            cpa16s(base + NNF_B + row * 144 + cc * 16, B + (size_t)(k0 + row) * N + n0 + cc * 8);
        }
        cpa_commit();
    };

    issue(0);
    issue(1);
    for (int s = 0; s < S; s++) {
        if (s + 1 < S) cpa_wait1(); else cpa_wait0();
        __syncthreads();
        if (s + 2 < S) issue(s + 2);
        const uint32_t base = sbase + (s % NNF_STAGES) * NNF_BUF;
        #pragma unroll
        for (int ks = 0; ks < 2; ks++) {
            uint32_t a[2][4];
            #pragma unroll
            for (int mt = 0; mt < 2; mt++) {
                uint32_t addr = base + NNF_A
                    + (uint32_t)(wm + mt * 16 + (lane & 15)) * 80
                    + (uint32_t)(ks * 32 + (lane >> 4) * 16);
                LDSM4(a[mt], addr);
            }
            uint32_t b[2][4];
            #pragma unroll
            for (int bt = 0; bt < 2; bt++) {
                uint32_t addr = base + NNF_B
                    + (uint32_t)(ks * 16 + (lane & 15)) * 144
                    + (uint32_t)((wn + bt * 16) * 2 + (lane >> 4) * 16);
                LDSM4T(b[bt], addr);
            }
            #pragma unroll
            for (int mt = 0; mt < 2; mt++)
                #pragma unroll
                for (int nt = 0; nt < 4; nt++)
                    MMA_FP16(c[mt][nt], a[mt], (&b[nt >> 1][(nt & 1) * 2]));
        }
    }

    #pragma unroll
    for (int mt = 0; mt < 2; mt++)
        #pragma unroll
        for (int nt = 0; nt < 4; nt++) {
            int row = m0 + wm + mt * 16 + g;
            int col = n0 + wn + nt * 8 + 2 * t;
            float2 v0 = make_float2(alpha * c[mt][nt][0], alpha * c[mt][nt][1]);
            float2 v1 = make_float2(alpha * c[mt][nt][2], alpha * c[mt][nt][3]);
            *(float2*)&C[(size_t)row * N + col]       = v0;
            *(float2*)&C[(size_t)(row + 8) * N + col] = v1;
        }
}

// ============================================================================
// convert: fp32 -> fp16 (vectorized)
// ============================================================================
__global__ void convert_f16(const float4* __restrict__ src, __half2* __restrict__ h2)
{
    const int i = blockIdx.x * 256 + threadIdx.x;
    float4 v = src[i];
    h2[2*i]     = __floats2half2_rn(v.x, v.y);
    h2[2*i + 1] = __floats2half2_rn(v.z, v.w);
}

// ============================================================================
// NT GEMM (tf32 split) producing fp16 h: h = (A @ W^T + bias + add)*scale
// ============================================================================
__global__ __launch_bounds__(256, 2)
void gemm_nt_h(const float* __restrict__ A, const float* __restrict__ W,
               const float* __restrict__ bias, const float* __restrict__ add,
               __half* __restrict__ outf, int M, int N, int K, float scale)
{
    const int m0 = blockIdx.y * 128, n0 = blockIdx.x * 64;
    const int tid = threadIdx.x, lane = tid & 31, wid = tid >> 5;
    const int wm = (wid & 3) * 32, wn = (wid >> 2) * 32;
    const int g = lane >> 2, t = lane & 3;

    __shared__ float As[2][128][20];
    __shared__ float Ws[2][64][20];

    float c[2][4][4] = {};
    const int S = K / 16;

    auto issue = [&](int s, int buf) {
        const int k0 = s * 16;
        #pragma unroll
        for (int j = 0; j < 2; j++) {
            int ch = tid + j * 256;
            int row = ch >> 2, kc = ch & 3;
            cpa16(&As[buf][row][kc * 4], A + (size_t)(m0 + row) * K + k0 + kc * 4);
        }
        int wrow = tid >> 2, wkc = tid & 3;
        cpa16(&Ws[buf][wrow][wkc * 4], W + (size_t)(n0 + wrow) * K + k0 + wkc * 4);
        cpa_commit();
    };

    issue(0, 0);
    for (int s = 0; s < S; s++) {
        if (s + 1 < S) { issue(s + 1, (s + 1) & 1); cpa_wait1(); }
        else cpa_wait0();
        __syncthreads();
        const int buf = s & 1;
        #pragma unroll
        for (int kf = 0; kf < 2; kf++) {
            uint32_t ah[2][4], al[2][4];
            #pragma unroll
            for (int mt = 0; mt < 2; mt++) {
                int mr = wm + mt * 16 + g;
                split_tf32(As[buf][mr    ][kf*8 + t],     ah[mt][0], al[mt][0]);
                split_tf32(As[buf][mr + 8][kf*8 + t],     ah[mt][1], al[mt][1]);
                split_tf32(As[buf][mr    ][kf*8 + t + 4], ah[mt][2], al[mt][2]);
                split_tf32(As[buf][mr + 8][kf*8 + t + 4], ah[mt][3], al[mt][3]);
            }
            uint32_t bh[4][2], bl[4][2];
            #pragma unroll
            for (int nt = 0; nt < 4; nt++) {
                int nr = wn + nt * 8 + g;
                split_tf32(Ws[buf][nr][kf*8 + t],     bh[nt][0], bl[nt][0]);
                split_tf32(Ws[buf][nr][kf*8 + t + 4], bh[nt][1], bl[nt][1]);
            }
            #pragma unroll
            for (int mt = 0; mt < 2; mt++)
                #pragma unroll
                for (int nt = 0; nt < 4; nt++)
                    MMA_TF32(c[mt][nt], ah[mt], bh[nt]);
            #pragma unroll
            for (int mt = 0; mt < 2; mt++)
                #pragma unroll
                for (int nt = 0; nt < 4; nt++)
                    MMA_TF32(c[mt][nt], ah[mt], bl[nt]);
            #pragma unroll
            for (int mt = 0; mt < 2; mt++)
                #pragma unroll
                for (int nt = 0; nt < 4; nt++)
                    MMA_TF32(c[mt][nt], al[mt], bh[nt]);
        }
        __syncthreads();
    }

    #pragma unroll
    for (int mt = 0; mt < 2; mt++)
        #pragma unroll
        for (int nt = 0; nt < 4; nt++) {
            int row = m0 + wm + mt * 16 + g;
            int col = n0 + wn + nt * 8 + 2 * t;
            float2 bv = *(const float2*)&bias[col];
            size_t i0 = (size_t)row * N + col;
            size_t i1 = (size_t)(row + 8) * N + col;
            float2 d0 = *(const float2*)&add[i0];
            float2 d1 = *(const float2*)&add[i1];
            float v00 = (c[mt][nt][0] + bv.x + d0.x) * scale;
            float v01 = (c[mt][nt][1] + bv.y + d0.y) * scale;
            float v10 = (c[mt][nt][2] + bv.x + d1.x) * scale;
            float v11 = (c[mt][nt][3] + bv.y + d1.y) * scale;
            *(__half2*)&outf[i0] = __floats2half2_rn(v00, v01);
            *(__half2*)&outf[i1] = __floats2half2_rn(v10, v11);
        }
}

// ============================================================================
// NT GEMM with fp32 epilogue (final output): out = (A @ W^T + bias + add)*scale
// ============================================================================
__global__ __launch_bounds__(256, 2)
void gemm_nt_tc(const float* __restrict__ A, const float* __restrict__ W,
                const float* __restrict__ bias, const float* __restrict__ add,
                float* __restrict__ out, int M, int N, int K, float scale)
{
    const int m0 = blockIdx.y * 128, n0 = blockIdx.x * 64;
    const int tid = threadIdx.x, lane = tid & 31, wid = tid >> 5;
    const int wm = (wid & 3) * 32, wn = (wid >> 2) * 32;
    const int g = lane >> 2, t = lane & 3;

    __shared__ float As[2][128][20];
    __shared__ float Ws[2][64][20];

    float c[2][4][4] = {};
    const int S = K / 16;

    auto issue = [&](int s, int buf) {
        const int k0 = s * 16;
        #pragma unroll
        for (int j = 0; j < 2; j++) {
            int ch = tid + j * 256;
            int row = ch >> 2, kc = ch & 3;
            cpa16(&As[buf][row][kc * 4], A + (size_t)(m0 + row) * K + k0 + kc * 4);
        }
        int wrow = tid >> 2, wkc = tid & 3;
        cpa16(&Ws[buf][wrow][wkc * 4], W + (size_t)(n0 + wrow) * K + k0 + wkc * 4);
        cpa_commit();
    };

    issue(0, 0);
    for (int s = 0; s < S; s++) {
        if (s + 1 < S) { issue(s + 1, (s + 1) & 1); cpa_wait1(); }
        else cpa_wait0();
        __syncthreads();
        const int buf = s & 1;
        #pragma unroll
        for (int kf = 0; kf < 2; kf++) {
            uint32_t ah[2][4], al[2][4];
            #pragma unroll
            for (int mt = 0; mt < 2; mt++) {
                int mr = wm + mt * 16 + g;
                split_tf32(As[buf][mr    ][kf*8 + t],     ah[mt][0], al[mt][0]);
                split_tf32(As[buf][mr + 8][kf*8 + t],     ah[mt][1], al[mt][1]);
                split_tf32(As[buf][mr    ][kf*8 + t + 4], ah[mt][2], al[mt][2]);
                split_tf32(As[buf][mr + 8][kf*8 + t + 4], ah[mt][3], al[mt][3]);
            }
            uint32_t bh[4][2], bl[4][2];
            #pragma unroll
            for (int nt = 0; nt < 4; nt++) {
                int nr = wn + nt * 8 + g;
                split_tf32(Ws[buf][nr][kf*8 + t],     bh[nt][0], bl[nt][0]);
                split_tf32(Ws[buf][nr][kf*8 + t + 4], bh[nt][1], bl[nt][1]);
            }
            #pragma unroll
            for (int mt = 0; mt < 2; mt++)
                #pragma unroll
                for (int nt = 0; nt < 4; nt++)
                    MMA_TF32(c[mt][nt], ah[mt], bh[nt]);
            #pragma unroll
            for (int mt = 0; mt < 2; mt++)
                #pragma unroll
                for (int nt = 0; nt < 4; nt++)
                    MMA_TF32(c[mt][nt], ah[mt], bl[nt]);
            #pragma unroll
            for (int mt = 0; mt < 2; mt++)
                #pragma unroll
                for (int nt = 0; nt < 4; nt++)
                    MMA_TF32(c[mt][nt], al[mt], bh[nt]);
        }
        __syncthreads();
    }

    #pragma unroll
    for (int mt = 0; mt < 2; mt++)
        #pragma unroll
        for (int nt = 0; nt < 4; nt++) {
            int row = m0 + wm + mt * 16 + g;
            int col = n0 + wn + nt * 8 + 2 * t;
            float2 bv = *(const float2*)&bias[col];
            size_t i0 = (size_t)row * N + col;
            size_t i1 = (size_t)(row + 8) * N + col;
            float2 d0 = *(const float2*)&add[i0];
            float2 d1 = *(const float2*)&add[i1];
            float2 v0 = make_float2((c[mt][nt][0] + bv.x + d0.x) * scale,
                                    (c[mt][nt][1] + bv.y + d0.y) * scale);
            float2 v1 = make_float2((c[mt][nt][2] + bv.x + d1.x) * scale,
                                    (c[mt][nt][3] + bv.y + d1.y) * scale);
            *(float2*)&out[i0] = v0;
            *(float2*)&out[i1] = v1;
        }
}

// ---------------- row softmax (in place) + fp16 copy ------------------------
__global__ void softmax_f16(float* __restrict__ attn, __half* __restrict__ af)
{
    const size_t row = blockIdx.x;
    float* p = attn + row * (size_t)Sc;
    __half* pf = af + row * (size_t)Sc;
    const int tid = threadIdx.x;   // 256 threads, 8 elems each
    __shared__ float red[256];
    float v[8];
    float mx = -CUDART_INF_F;
    #pragma unroll
    for (int i = 0; i < 8; i++) { v[i] = p[tid + i*256]; mx = fmaxf(mx, v[i]); }
    red[tid] = mx; __syncthreads();
    for (int s = 128; s > 0; s >>= 1) { if (tid < s) red[tid] = fmaxf(red[tid], red[tid+s]); __syncthreads(); }
    mx = red[0]; __syncthreads();
    float sum = 0.0f;
    #pragma unroll
    for (int i = 0; i < 8; i++) { v[i] = __expf(v[i] - mx); sum += v[i]; }
    red[tid] = sum; __syncthreads();
    for (int s = 128; s > 0; s >>= 1) { if (tid < s) red[tid] += red[tid+s]; __syncthreads(); }
    const float inv = 1.0f / red[0];
    #pragma unroll
    for (int i = 0; i < 8; i++) {
        float a = v[i] * inv;
        p[tid + i*256] = a;
        pf[tid + i*256] = __float2half_rn(a);
    }
}

// ---------------- x_mean[b][s] = mean_t attn[b][t][s] -----------------------
__global__ void xmean_k(const float* __restrict__ attn)
{
    const int b = blockIdx.y;
    const int s = blockIdx.x * 256 + threadIdx.x;
    const float* p = attn + (size_t)b * Tc * Sc + s;
    float sum = 0.0f;
    for (int t = 0; t < Tc; t++) sum += p[(size_t)t * Sc];
    g_xmean[b * Sc + s] = sum * (1.0f / Tc);
}

// ---------------- row inv-norms of strided enc_values + aa -----------------
__global__ void norm_aa_k(const float* __restrict__ V)
{
    const int b = blockIdx.x;
    const int w = threadIdx.x >> 5, lane = threadIdx.x & 31;
    for (int n = w; n < NSEL; n += 8) {
        const float* row = V + ((size_t)b * Sc + (size_t)n * STRIDEc) * Ec;
        float s = 0.0f;
        for (int e = lane; e < Ec; e += 32) { float x = row[e]; s = fmaf(x, x, s); }
        #pragma unroll
        for (int o = 16; o; o >>= 1) s += __shfl_down_sync(0xffffffffu, s, o);
        if (lane == 0) {
            g_invn[b * NSEL + n] = rsqrtf(s);
            g_aa[b * NSEL + n]   = g_xmean[b * Sc + n * STRIDEc];
        }
    }
}

// ---------------- L[b][n][m] = aa_n aa_m * <v_n,v_m>/(|v_n||v_m|) ----------
__global__ void L_k(const float* __restrict__ V)
{
    const int b = blockIdx.x, n = blockIdx.y;
    __shared__ float vn[Ec];
    const float* rn = V + ((size_t)b * Sc + (size_t)n * STRIDEc) * Ec;
    for (int e = threadIdx.x; e < Ec; e += 128) vn[e] = rn[e];
    __syncthreads();
    const int m = threadIdx.x;
    if (m < NSEL) {
        const float* rm = V + ((size_t)b * Sc + (size_t)m * STRIDEc) * Ec;
        float d = 0.0f;
        for (int e = 0; e < Ec; e++) d = fmaf(vn[e], rm[e], d);
        float val = d * g_invn[b*NSEL + n] * g_invn[b*NSEL + m]
                      * g_aa[b*NSEL + n]   * g_aa[b*NSEL + m];
        g_L[((size_t)b * NSEL + n) * NSEL + m] = val;
    }
}

// numpy-style argmax of logf(D[n]*mask[n]): first NaN wins; strict > keeps first max
__device__ __forceinline__ int argmax_logDm(const float* D, const float* msk)
{
    int J = 0; float best = -CUDART_INF_F; bool done = false;
    for (int n = 0; n < NSEL && !done; n++) {
        float v = logf(D[n] * msk[n]);
        if (isnan(v)) { J = n; done = true; }
        else if (v > best) { best = v; J = n; }
    }
    return J;
}

// ---------------- greedy bfgm selection (sequential, tiny) -----------------
__global__ void bfgm_k()
{
    const int b = blockIdx.x, tid = threadIdx.x;  // 128 threads
    __shared__ float Cm[NSEL][MS];
    __shared__ float D[NSEL], msk[NSEL], cjs[MS];
    __shared__ float djs;
    __shared__ int Jsh, sel[MS];
    const float* L = g_L + (size_t)b * NSEL * NSEL;

    if (tid < NSEL) {
        D[tid] = L[(size_t)tid * NSEL + tid];
        msk[tid] = 1.0f;
        #pragma unroll
        for (int k = 0; k < MS; k++) Cm[tid][k] = 0.0f;
    }
    __syncthreads();
    if (tid == 0) {
        int J = argmax_logDm(D, msk);
        Jsh = J; msk[J] = 0.0f; sel[0] = J;
    }
    __syncthreads();

    for (int t = 1; t < MS; t++) {
        const int J = Jsh;
        if (tid < MS) cjs[tid] = Cm[J][tid];
        if (tid == 0) djs = D[J];
        __syncthreads();
        if (tid < NSEL) {
            float Lj = L[(size_t)J * NSEL + tid];
            float cd = 0.0f;
            #pragma unroll
            for (int k = 0; k < MS; k++) cd = fmaf(Cm[tid][k], cjs[k], cd);
            float e = (Lj - cd) / djs * msk[tid];
            Cm[tid][t] = e;
            D[tid] -= e * e;
        }
        __syncthreads();
        if (tid == 0) {
            int Jn = argmax_logDm(D, msk);
            Jsh = Jn; msk[Jn] = 0.0f; sel[t] = Jn;
        }
        __syncthreads();
    }
    if (tid == 0) {
        for (int i = 1; i < MS; i++) {          // insertion sort ascending
            int key = sel[i], j = i - 1;
            while (j >= 0 && sel[j] > key) { sel[j+1] = sel[j]; j--; }
            sel[j+1] = key;
        }
        for (int k = 0; k < MS; k++) g_mu[b*MS + k] = sel[k];
    }
}

// ---------------- gaussian mixture -> softmax(dist) -> KL partial ----------
__global__ void distkl_k()
{
    const int b = blockIdx.x, tid = threadIdx.x;   // 256 threads, 8 s-values each
    __shared__ float red[256];
    int mus[MS];
    #pragma unroll
    for (int k = 0; k < MS; k++) mus[k] = g_mu[b*MS + k];

    float g[8];
    float mx = -CUDART_INF_F;
    #pragma unroll
    for (int i = 0; i < 8; i++) {
        const int s = tid + i*256;
        float acc = 0.0f;
        #pragma unroll
        for (int k = 0; k < MS; k++) {
            float z = (float)s - (float)mus[k];
            acc += expf(-z*z * (1.0f/18.0f));        // 2*sigma^2 = 18
        }
        acc *= 0.13298076013381091f;                 // 1/(sqrt(2pi)*3)
        g[i] = acc; mx = fmaxf(mx, acc);
    }
    red[tid] = mx; __syncthreads();
    for (int s = 128; s > 0; s >>= 1) { if (tid < s) red[tid] = fmaxf(red[tid], red[tid+s]); __syncthreads(); }
    mx = red[0]; __syncthreads();
    float sum = 0.0f;
    #pragma unroll
    for (int i = 0; i < 8; i++) { g[i] = expf(g[i] - mx); sum += g[i]; }
    red[tid] = sum; __syncthreads();
    for (int s = 128; s > 0; s >>= 1) { if (tid < s) red[tid] += red[tid+s]; __syncthreads(); }
    const float inv = 1.0f / red[0];
    __syncthreads();

    float kl = 0.0f;
    #pragma unroll
    for (int i = 0; i < 8; i++) {
        const int s = tid + i*256;
        float xm = g_xmean[b*Sc + s];
        kl += xm * (logf(xm) - g[i] * inv);
    }
    red[tid] = kl; __syncthreads();
    for (int s = 128; s > 0; s >>= 1) { if (tid < s) red[tid] += red[tid+s]; __syncthreads(); }
    if (tid == 0) atomicAdd(&g_kl, red[0]);
}

// ---------------- launch ----------------------------------------------------
extern "C" void kernel_launch(void* const* d_in, const int* in_sizes, int n_in,
                              void* d_out, int out_size)
{
    const float* x  = (const float*)d_in[0];
    const float* te = (const float*)d_in[1];
    const float* ek = (const float*)d_in[2];   // [B,E,S]
    const float* ev = (const float*)d_in[3];   // [B,S,E]
    const float* Wi = (const float*)d_in[4];   // [E,C]
    const float* bi = (const float*)d_in[5];
    const float* Wo = (const float*)d_in[6];   // [C,E]
    const float* bo = (const float*)d_in[7];

    float* out  = (float*)d_out;                              // [B,T,C]
    float* attn = out + (size_t)Bc * Tc * Cc;                 // [B,T,S]
    float* klp  = attn + (size_t)Bc * Tc * Sc;                // scalar

    float* hbuf = nullptr;
    cudaGetSymbolAddress((void**)&hbuf, g_h);
    __half *hf, *ekf, *evf, *af;
    cudaGetSymbolAddress((void**)&hf,  g_hf);
    cudaGetSymbolAddress((void**)&ekf, g_ekf);
    cudaGetSymbolAddress((void**)&evf, g_evf);
    cudaGetSymbolAddress((void**)&af,  g_af);

    cudaFuncSetAttribute(gemm_nn_fp16, cudaFuncAttributeMaxDynamicSharedMemorySize, NNF_SMEM);

    const float SQ05 = 0.70710678118654752f;
    const float SQS  = 45.25483399593904f;    // s*sqrt(1/s), s=2048

    // converts first (so the big NN GEMM lands in the ncu capture slot)
    const int nEK4 = Bc * Ec * Sc / 4;  // per float4
    convert_f16<<<nEK4 / 256, 256>>>((const float4*)ek, (__half2*)ekf);
    convert_f16<<<nEK4 / 256, 256>>>((const float4*)ev, (__half2*)evf);

    // h = (x @ W_in^T + b_in + te) * sqrt(0.5)  -> fp16
    gemm_nt_h<<<dim3(Ec/64, (Bc*Tc)/128), 256>>>(x, Wi, bi, te, hf, Bc*Tc, Ec, Cc, SQ05);

    // scores = h @ enc_keys (fp16, fp32 acc), write into attn region
    gemm_nn_fp16<<<dim3(Sc/64, Tc/128, Bc), 256, NNF_SMEM>>>(
        hf, ekf, attn, Tc, Sc, Ec,
        (long long)Tc*Ec, (long long)Ec*Sc, (long long)Tc*Sc, 1.0f);

    // attn = softmax(scores) in place + fp16 copy
    softmax_f16<<<Bc*Tc, 256>>>(attn, af);

    // x_mean
    xmean_k<<<dim3(Sc/256, Bc), 256>>>(attn);

    // out1 = attn @ enc_values * sqrt(S)  (fp16, fp32 out into g_h)
    gemm_nn_fp16<<<dim3(Ec/64, Tc/128, Bc), 256, NNF_SMEM>>>(
        af, evf, hbuf, Tc, Ec, Sc,
        (long long)Tc*Sc, (long long)Sc*Ec, (long long)Tc*Ec, SQS);

    // out = (out1 @ W_out^T + b_out + x) * sqrt(0.5)
    gemm_nt_tc<<<dim3(Cc/64, (Bc*Tc)/128), 256>>>(hbuf, Wo, bo, x, out, Bc*Tc, Cc, Ec, SQ05);

    // DPP side path
    init_k<<<1, 1>>>();
    norm_aa_k<<<Bc, 256>>>(ev);
    L_k<<<dim3(Bc, NSEL), 128>>>(ev);
    bfgm_k<<<Bc, 128>>>();
    distkl_k<<<Bc, 256>>>();
    final_k<<<1, 1>>>(klp);
}